// round 17
// baseline (speedup 1.0000x reference)
#include <cuda_runtime.h>

// FeatNeighbourCorr R13 (= R12 resubmit after infra failure):
// 2x4-patch compute (R11 core) in a 32x32 tile, NT=128, KC=2,
// 2-stage cp.async pipeline (R5 skeleton).
// out[b,k,h,w] = <n_p, n_q>, n = f/||f||_C, q = reflect(p - d_k).

#define HH 256
#define WW 256
#define CC 128
#define HW (HH * WW)
#define TH 32
#define TW 32
#define KC 2
#define NCH (CC / KC)        // 64 iterations
#define SR 34                // staged rows h0-1..h0+32
#define SPC 18               // staged float2/row: cols w0-2..w0+33
#define SSTR2 20             // float2 stride (160B rows, 16B-aligned)
#define SSTRF 40             // float stride
#define PLANE2 (SR * SSTR2)  // 680 f2 per channel plane
#define BUF2 (KC * PLANE2)   // 1360 f2 per buffer
#define NSLOTC (SR * SPC)    // 612 pair slots per channel
#define NT 128
#define RNSTR 36

typedef unsigned long long u64;

__device__ __forceinline__ u64 pack2(float lo, float hi) {
    u64 r; asm("mov.b64 %0, {%1,%2};" : "=l"(r) : "f"(lo), "f"(hi)); return r;
}
__device__ __forceinline__ float lo2(u64 a) { return __uint_as_float((unsigned)a); }
__device__ __forceinline__ float hi2(u64 a) { return __uint_as_float((unsigned)(a >> 32)); }
__device__ __forceinline__ void fma2(u64& d, u64 a, u64 b) {
    asm("fma.rn.f32x2 %0, %1, %2, %0;" : "+l"(d) : "l"(a), "l"(b));
}
__device__ __forceinline__ u64 mul2(u64 a, u64 b) {
    u64 r; asm("mul.rn.f32x2 %0, %1, %2;" : "=l"(r) : "l"(a), "l"(b)); return r;
}
__device__ __forceinline__ int refl(int x) {
    return x < 0 ? -x : (x > HH - 1 ? 2 * (HH - 1) - x : x);
}

__global__ __launch_bounds__(NT, 3)
void featcorr_r13(const float* __restrict__ feats, float* __restrict__ out) {
    __shared__ alignas(16) u64 pool[2 * BUF2];   // 21760 B
    const int t  = threadIdx.x;
    const int b  = blockIdx.z;
    const int h0 = blockIdx.y * TH;
    const int w0 = blockIdx.x * TW;
    const unsigned sbase = (unsigned)__cvta_generic_to_shared(pool);

    // ---- cp.async pair slots (per channel; ch offsets added at issue) ----
    int src[5]; unsigned dst[5]; bool val[5];
#pragma unroll
    for (int u = 0; u < 5; ++u) {
        int s = t + NT * u;
        bool in = s < NSLOTC;
        int ss = in ? s : 0;
        int row = ss / SPC, pc = ss - row * SPC;
        int gh = refl(h0 - 1 + row);
        int gc = w0 - 2 + 2 * pc;
        bool edge = (gc < 0) || (gc >= WW - 1);   // pair straddles border
        val[u] = in && !edge;
        src[u] = gh * WW + gc;
        dst[u] = sbase + (unsigned)((row * SSTR2 + pc) * 8);
    }

    // ---- scalar slots for reflected w-edge pairs (68 slots on edge tiles) ----
    const bool eact = (w0 == 0 || w0 == WW - TW) && (t < KC * SR);
    int es0 = 0, eidx = 0;
    if (eact) {
        int ch = t / SR, row = t - ch * SR;
        int gh = refl(h0 - 1 + row);
        if (w0 == 0) { es0 = ch * HW + gh * WW + 2;   eidx = ch * PLANE2 + row * SSTR2 + 0; }
        else         { es0 = ch * HW + gh * WW + 254; eidx = ch * PLANE2 + row * SSTR2 + 17; }
    }

    // ---- halo-ring ssq slots (132 ring pixels, up to 2 per thread) ----
    int roff[2], rnoff[2]; bool ract[2];
#pragma unroll
    for (int u = 0; u < 2; ++u) {
        int s = t + NT * u;
        ract[u] = s < 132;
        int ss = ract[u] ? s : 0;
        int rrow, rcol;
        if (ss < 34)       { rrow = 0;        rcol = 1 + ss; }
        else if (ss < 68)  { rrow = SR - 1;   rcol = ss - 33; }
        else if (ss < 100) { rrow = ss - 67;  rcol = 1; }
        else               { rrow = ss - 99;  rcol = 34; }
        roff[u]  = rrow * SSTRF + rcol;
        rnoff[u] = rrow * RNSTR + rcol;
    }

    // thread -> 2x4 patch: output rows 2g, 2g+1; cols fx..fx+3
    const int g = t >> 3, x = t & 7;
    const int fx = 4 * x;

    u64 accA[8], accB[8], accC[8], accD[8];
#pragma unroll
    for (int k = 0; k < 8; ++k) { accA[k] = accB[k] = accC[k] = accD[k] = 0ull; }
    u64 sq0 = 0, sq1 = 0, sq2 = 0, sq3 = 0;
    float rss0 = 0.f, rss1 = 0.f;
    float ex = 0.f, ey = 0.f;

    const float* bp = feats + (size_t)b * CC * HW;

    // ---- prologue: chunk 0 into buffer 0 ----
    {
#pragma unroll
        for (int u = 0; u < 5; ++u) {
            if (val[u]) {
#pragma unroll
                for (int ch = 0; ch < KC; ++ch)
                    asm volatile("cp.async.ca.shared.global [%0], [%1], 8;"
                                 :: "r"(dst[u] + (unsigned)(ch * PLANE2 * 8)),
                                    "l"(bp + src[u] + ch * HW) : "memory");
            }
        }
        asm volatile("cp.async.commit_group;" ::: "memory");
        if (eact) { ex = __ldg(bp + es0); ey = __ldg(bp + es0 - 1); }
    }

    for (int it = 0; it < NCH; ++it) {
        asm volatile("cp.async.wait_group 0;" ::: "memory");
        if (eact)
            reinterpret_cast<float2*>(pool)[(it & 1) * BUF2 + eidx] = make_float2(ex, ey);
        __syncthreads();

        if (it + 1 < NCH) {
            const float* bn = bp + KC * HW;
            const unsigned bo = (unsigned)(((it + 1) & 1) * BUF2 * 8);
#pragma unroll
            for (int u = 0; u < 5; ++u) {
                if (val[u]) {
#pragma unroll
                    for (int ch = 0; ch < KC; ++ch)
                        asm volatile("cp.async.ca.shared.global [%0], [%1], 8;"
                                     :: "r"(dst[u] + bo + (unsigned)(ch * PLANE2 * 8)),
                                        "l"(bn + src[u] + ch * HW) : "memory");
                }
            }
            asm volatile("cp.async.commit_group;" ::: "memory");
            if (eact) { ex = __ldg(bn + es0); ey = __ldg(bn + es0 - 1); }
        }

        const float* Bf = reinterpret_cast<const float*>(pool + (it & 1) * BUF2);
#pragma unroll
        for (int ch = 0; ch < KC; ++ch) {
            const float* P = Bf + ch * (PLANE2 * 2) + (2 * g) * SSTRF + fx;
            float4 Ar[4], Br[4];
#pragma unroll
            for (int i = 0; i < 4; ++i) {
                Ar[i] = *reinterpret_cast<const float4*>(P + i * SSTRF);
                Br[i] = *reinterpret_cast<const float4*>(P + i * SSTRF + 4);
            }
            u64 M1[4], M2[4], L1[4], L2[4], R2[4];
#pragma unroll
            for (int i = 0; i < 4; ++i) {
                M1[i] = pack2(Ar[i].z, Ar[i].w);
                M2[i] = pack2(Br[i].x, Br[i].y);
                L1[i] = pack2(Ar[i].y, Ar[i].z);
                L2[i] = pack2(Ar[i].w, Br[i].x);
                R2[i] = pack2(Br[i].y, Br[i].z);
            }
            // output row 0 (center staged row 2g+1)
            fma2(accA[0], M1[1], M1[0]); fma2(accB[0], M2[1], M2[0]);
            fma2(accA[1], M1[1], L1[0]); fma2(accB[1], M2[1], L2[0]);
            fma2(accA[2], M1[1], L1[1]); fma2(accB[2], M2[1], L2[1]);
            fma2(accA[3], M1[1], L1[2]); fma2(accB[3], M2[1], L2[2]);
            fma2(accA[4], M1[1], M1[2]); fma2(accB[4], M2[1], M2[2]);
            fma2(accA[5], M1[1], L2[2]); fma2(accB[5], M2[1], R2[2]);
            fma2(accA[6], M1[1], L2[1]); fma2(accB[6], M2[1], R2[1]);
            fma2(accA[7], M1[1], L2[0]); fma2(accB[7], M2[1], R2[0]);
            // output row 1 (center staged row 2g+2)
            fma2(accC[0], M1[2], M1[1]); fma2(accD[0], M2[2], M2[1]);
            fma2(accC[1], M1[2], L1[1]); fma2(accD[1], M2[2], L2[1]);
            fma2(accC[2], M1[2], L1[2]); fma2(accD[2], M2[2], L2[2]);
            fma2(accC[3], M1[2], L1[3]); fma2(accD[3], M2[2], L2[3]);
            fma2(accC[4], M1[2], M1[3]); fma2(accD[4], M2[2], M2[3]);
            fma2(accC[5], M1[2], L2[3]); fma2(accD[5], M2[2], R2[3]);
            fma2(accC[6], M1[2], L2[2]); fma2(accD[6], M2[2], R2[2]);
            fma2(accC[7], M1[2], L2[1]); fma2(accD[7], M2[2], R2[1]);
            // sum-of-squares for own pixels
            fma2(sq0, M1[1], M1[1]); fma2(sq1, M2[1], M2[1]);
            fma2(sq2, M1[2], M1[2]); fma2(sq3, M2[2], M2[2]);
            // ring ssq
#pragma unroll
            for (int u = 0; u < 2; ++u) {
                if (ract[u]) {
                    float rv = Bf[ch * (PLANE2 * 2) + roff[u]];
                    if (u) rss1 += rv * rv; else rss0 += rv * rv;
                }
            }
        }
        bp += KC * HW;
    }

    // ---- rsqrt + RN map (aliased over buffer 0) ----
    float rn00 = rsqrtf(lo2(sq0)), rn01 = rsqrtf(hi2(sq0));
    float rn02 = rsqrtf(lo2(sq1)), rn03 = rsqrtf(hi2(sq1));
    float rn10 = rsqrtf(lo2(sq2)), rn11 = rsqrtf(hi2(sq2));
    float rn12 = rsqrtf(lo2(sq3)), rn13 = rsqrtf(hi2(sq3));
    float* RN = reinterpret_cast<float*>(pool);   // 34 x 36 floats = 4896 B
    *reinterpret_cast<float2*>(RN + (2 * g + 1) * RNSTR + fx + 2) = make_float2(rn00, rn01);
    *reinterpret_cast<float2*>(RN + (2 * g + 1) * RNSTR + fx + 4) = make_float2(rn02, rn03);
    *reinterpret_cast<float2*>(RN + (2 * g + 2) * RNSTR + fx + 2) = make_float2(rn10, rn11);
    *reinterpret_cast<float2*>(RN + (2 * g + 2) * RNSTR + fx + 4) = make_float2(rn12, rn13);
    if (ract[0]) RN[rnoff[0]] = rsqrtf(rss0);
    if (ract[1]) RN[rnoff[1]] = rsqrtf(rss1);
    __syncthreads();

    // ---- epilogue: gather neighbor norms, scale, store ----
    const int DXa[8] = {1, 1, 0, -1, -1, -1, 0, 1};
    const int DYa[8] = {0, 1, 1, 1, 0, -1, -1, -1};
    const int wbase = w0 + fx;
    float* ob = out + ((size_t)b * 8) * HW;
    const u64 rpA0 = pack2(rn00, rn01), rpB0 = pack2(rn02, rn03);
    const u64 rpA1 = pack2(rn10, rn11), rpB1 = pack2(rn12, rn13);
#pragma unroll
    for (int j = 0; j < 2; ++j) {
        const int h = h0 + 2 * g + j;
        const u64 rpA = j ? rpA1 : rpA0;
        const u64 rpB = j ? rpB1 : rpB0;
#pragma unroll
        for (int k = 0; k < 8; ++k) {
            int qrow = refl(h - DXa[k]) - h0 + 1;
            float rq[4];
#pragma unroll
            for (int i = 0; i < 4; ++i) {
                int qw = refl(wbase + i - DYa[k]);
                rq[i] = RN[qrow * RNSTR + (qw - w0 + 2)];
            }
            u64 aP = j ? accC[k] : accA[k];
            u64 aQ = j ? accD[k] : accB[k];
            u64 o1 = mul2(mul2(aP, rpA), pack2(rq[0], rq[1]));
            u64 o2 = mul2(mul2(aQ, rpB), pack2(rq[2], rq[3]));
            *reinterpret_cast<float4*>(ob + (size_t)k * HW + (size_t)h * WW + wbase) =
                make_float4(lo2(o1), hi2(o1), lo2(o2), hi2(o2));
        }
    }
}

extern "C" void kernel_launch(void* const* d_in, const int* in_sizes, int n_in,
                              void* d_out, int out_size) {
    const float* feats = (const float*)d_in[0];
    float* out = (float*)d_out;
    dim3 grid(WW / TW, HH / TH, 8);
    featcorr_r13<<<grid, NT>>>(feats, out);
}